// round 15
// baseline (speedup 1.0000x reference)
#include <cuda_runtime.h>
#include <math.h>

#define GMX 32
#define GHALF 16
#define NMAX 22528
#define LCAP 2048
#define FCAP 1024
#define TOPK_K 15
#define BG_LAB 15
#define PI_F   3.14159265358979323846f
#define HPI_F  1.57079632679489661923f

// -------- persistent device scratch (zero-init; left clean each run) --------
__device__ int g_cnt[GMX];
__device__ unsigned long long g_anchorKey[GMX];
__device__ int g_pairCnt;
__device__ float g_lv[GMX * LCAP];
__device__ int   g_li[GMX * LCAP];
__device__ unsigned g_pairs[GMX * LCAP];   // packed: i<<16 | g<<11 | pos
__device__ unsigned g_bits[NMAX];
__device__ int g_ovrPt[GMX];
__device__ int g_ovrG[GMX];
__device__ int g_ovrCnt;
__device__ volatile int g_selDone;
__device__ int g_done;

// ---------------------------------------------------------------------------
__device__ __forceinline__ float wadd(float v) {
#pragma unroll
    for (int off = 16; off > 0; off >>= 1) v += __shfl_xor_sync(0xFFFFFFFFu, v, off);
    return v;
}
__device__ __forceinline__ float wmaxf(float v) {
#pragma unroll
    for (int off = 16; off > 0; off >>= 1) v = fmaxf(v, __shfl_xor_sync(0xFFFFFFFFu, v, off));
    return v;
}

__device__ __forceinline__ void box_corner(int a, float cx, float cy, float w2, float h2,
                                           float c, float s, float& x, float& y) {
    float dxs = (a < 2) ? w2 : -w2;
    float dys = (a == 1 || a == 2) ? h2 : -h2;
    x = cx + dxs * c - dys * s;
    y = cy + dxs * s + dys * c;
}

// ---------------------------------------------------------------------------
// Warp-cooperative rotated IoU (validated R12). Lane k owns candidate slot k.
// ---------------------------------------------------------------------------
__device__ float riou_warp(int lane,
                           float b1cx, float b1cy, float b1w, float b1h,
                           float b1c, float b1s, float a1,
                           float b2cx, float b2cy, float b2w, float b2h,
                           float b2c, float b2s, float a2)
{
    {
        float ddx = b1cx - b2cx, ddy = b1cy - b2cy;
        float r1 = 0.5f * sqrtf(b1w * b1w + b1h * b1h);
        float r2 = 0.5f * sqrtf(b2w * b2w + b2h * b2h);
        float rrs = r1 + r2 + 0.5f;
        if (ddx * ddx + ddy * ddy > rrs * rrs) return 0.0f;
    }
    float w12 = b1w * 0.5f, h12 = b1h * 0.5f;
    float w22 = b2w * 0.5f, h22 = b2h * 0.5f;

    float ptx = 0.0f, pty = 0.0f;
    bool ok = false;

    if (lane < 16) {
        int a = lane >> 2, b = lane & 3;
        float px, py, pnx, pny, qx, qy, qnx, qny;
        box_corner(a, b1cx, b1cy, w12, h12, b1c, b1s, px, py);
        box_corner((a + 1) & 3, b1cx, b1cy, w12, h12, b1c, b1s, pnx, pny);
        box_corner(b, b2cx, b2cy, w22, h22, b2c, b2s, qx, qy);
        box_corner((b + 1) & 3, b2cx, b2cy, w22, h22, b2c, b2s, qnx, qny);
        float d1x = pnx - px, d1y = pny - py;
        float d2x = qnx - qx, d2y = qny - qy;
        float den = d1x * d2y - d1y * d2x;
        bool dok = fabsf(den) > 1e-10f;
        float safe = dok ? den : 1.0f;
        float qpx = qx - px, qpy = qy - py;
        float t = (qpx * d2y - qpy * d2x) / safe;
        float u = (qpx * d1y - qpy * d1x) / safe;
        ok = dok && t >= 0.0f && t <= 1.0f && u >= 0.0f && u <= 1.0f;
        ptx = px + t * d1x; pty = py + t * d1y;
    } else if (lane < 20) {
        int a = lane - 16;
        box_corner(a, b1cx, b1cy, w12, h12, b1c, b1s, ptx, pty);
        float rx = ptx - b2cx, ry = pty - b2cy;
        float xx = rx * b2c + ry * b2s;
        float yy = -rx * b2s + ry * b2c;
        ok = (fabsf(xx) <= w22 + 1e-6f) && (fabsf(yy) <= h22 + 1e-6f);
    } else if (lane < 24) {
        int b = lane - 20;
        box_corner(b, b2cx, b2cy, w22, h22, b2c, b2s, ptx, pty);
        float rx = ptx - b1cx, ry = pty - b1cy;
        float xx = rx * b1c + ry * b1s;
        float yy = -rx * b1s + ry * b1c;
        ok = (fabsf(xx) <= w12 + 1e-6f) && (fabsf(yy) <= h12 + 1e-6f);
    }

    unsigned okm = __ballot_sync(0xFFFFFFFFu, ok) & 0xFFFFFFu;
    if (okm == 0u) return 0.0f;
    int cnt = __popc(okm);

    float ctrx = wadd(ok ? ptx : 0.0f) / (float)cnt;
    float ctry = wadd(ok ? pty : 0.0f) / (float)cnt;

    float vx = ptx - ctrx, vy = pty - ctry;
    float dnm = fabsf(vx) + fabsf(vy);
    float pa = ok ? ((dnm == 0.0f) ? 0.0f : copysignf(1.0f - vx / dnm, vy)) : 3.0e38f;

    float mA = 3.0e38f, mX = 0.0f, mY = 0.0f;
    float bA = 3.0e38f, bX = 0.0f, bY = 0.0f;
    bool bFound = false;
#pragma unroll
    for (int j = 0; j < 24; ++j) {
        float paj = __shfl_sync(0xFFFFFFFFu, pa, j);
        float pxj = __shfl_sync(0xFFFFFFFFu, ptx, j);
        float pyj = __shfl_sync(0xFFFFFFFFu, pty, j);
        bool okj = (okm >> j) & 1u;
        if (okj && paj < mA) { mA = paj; mX = pxj; mY = pyj; }
        bool gtk = (paj > pa) || (paj == pa && j > lane);
        if (okj && gtk && paj < bA) { bA = paj; bX = pxj; bY = pyj; bFound = true; }
    }
    if (!bFound) { bX = mX; bY = mY; }

    float cross = 0.0f;
    if (ok) {
        float vbx = bX - ctrx, vby = bY - ctry;
        cross = vx * vby - vy * vbx;
    }
    float acc = wadd(cross);
    float inter = 0.5f * fabsf(acc);
    return inter / fmaxf(a1 + a2 - inter, 1e-8f);
}

// ---------------------------------------------------------------------------
// kGate: 2 blocks per 256-point chunk (16 gts each). [validated R12]
// ---------------------------------------------------------------------------
__global__ void __launch_bounds__(256)
kGate(const float* __restrict__ pts, const float* __restrict__ rr,
      const float* __restrict__ stride, const float* __restrict__ gtb,
      int N, int G)
{
    __shared__ float sg[GHALF * 8];
    __shared__ unsigned long long sA[GHALF];

    int tid = threadIdx.x;
    int half = blockIdx.x & 1;
    int pb = blockIdx.x >> 1;
    int g0 = half * GHALF;
    int gn = G - g0; if (gn > GHALF) gn = GHALF; if (gn < 0) gn = 0;

    if (tid < GHALF) {
        sA[tid] = 0ULL;
        if (tid < gn) {
            int gg = g0 + tid;
            float cx = gtb[gg * 5 + 0], cy = gtb[gg * 5 + 1];
            float w = gtb[gg * 5 + 2], h = gtb[gg * 5 + 3], a = gtb[gg * 5 + 4];
            sg[tid * 8 + 0] = cx; sg[tid * 8 + 1] = cy;
            sg[tid * 8 + 2] = w;  sg[tid * 8 + 3] = h;
            sg[tid * 8 + 4] = cosf(a); sg[tid * 8 + 5] = sinf(a);
            float mwh = fmaxf(w, h);
            sg[tid * 8 + 6] = 0.5f * mwh * mwh;
        } else {
            sg[tid * 8 + 0] = -1e30f; sg[tid * 8 + 1] = -1e30f;
            sg[tid * 8 + 6] = 0.0f;
        }
    }
    __syncthreads();

    int i = pb * 256 + tid;
    bool inb = (i < N);

    float px = 0.f, py = 0.f, st = 1.f, r0 = 0.f, r1 = 0.f;
    if (inb) {
        float2 p2 = ((const float2*)pts)[i];
        float2 rr2 = ((const float2*)rr)[i];
        px = p2.x; py = p2.y;
        st = stride[i];
        r0 = rr2.x; r1 = rr2.y;
    }
    float crad = 1.5f * st;

    unsigned mask = 0u;
    if (inb) {
        for (int g = 0; g < gn; ++g) {
            float dx = px - sg[g * 8 + 0], dy = py - sg[g * 8 + 1];
            if (dx * dx + dy * dy >= sg[g * 8 + 6]) continue;   // exact skip (validated)

            float w = sg[g * 8 + 2], h = sg[g * 8 + 3];
            float c = sg[g * 8 + 4], s = sg[g * 8 + 5];
            float ox = dx * c + dy * s;
            float oy = -dx * s + dy * c;
            float t0 = w * 0.5f + ox, t1 = h * 0.5f + oy;
            float t2 = w * 0.5f - ox, t3 = h * 0.5f - oy;
            float mn = fminf(fminf(t0, t1), fminf(t2, t3));
            float mx = fmaxf(fmaxf(t0, t1), fmaxf(t2, t3));
            float u = 2.0f * ox / w, v = 2.0f * oy / h;
            float cent = fmaxf(1.0f - sqrtf((u * u + v * v + 1e-8f) * 0.5f), 0.0f);
            bool valid = (mn > 0.0f) && (fabsf(ox) < crad) && (fabsf(oy) < crad)
                         && (mx >= r0) && (mx <= r1);
            if (valid) mask |= 1u << g;

            if (cent > 0.0f) {
                unsigned long long key =
                    ((unsigned long long)__float_as_uint(cent) << 32) | (unsigned)(~(unsigned)i);
                if (key > *((volatile unsigned long long*)&sA[g]))
                    atomicMax(&sA[g], key);
            }
        }
    }
    __syncthreads();
    if (tid < gn) {
        unsigned long long v = sA[tid];
        if (v != 0ULL) atomicMax(&g_anchorKey[g0 + tid], v);
    }

    while (mask) {
        int g = __ffs(mask) - 1;
        mask &= mask - 1u;
        int gg = g0 + g;
        int pos = atomicAdd(&g_cnt[gg], 1);
        int ppos = atomicAdd(&g_pairCnt, 1);
        if (pos < LCAP && ppos < GMX * LCAP) {
            g_li[gg * LCAP + pos] = i;
            g_pairs[ppos] = ((unsigned)i << 16) | ((unsigned)gg << 11) | (unsigned)pos;
        }
    }
}

// ---------------------------------------------------------------------------
// kCost: warp per pair. [validated R12, byte-identical]
// ---------------------------------------------------------------------------
__global__ void __launch_bounds__(256)
kCost(const float* __restrict__ pts, const float* __restrict__ stride,
      const float* __restrict__ gtb, const int* __restrict__ glab,
      const float* __restrict__ preds, const float* __restrict__ probs, int G)
{
    __shared__ float sg[GMX * 8];
    __shared__ int sl[GMX];
    int tid = threadIdx.x;
    int lane = tid & 31;
    int wid = tid >> 5;
    if (tid < G) {
        float cx = gtb[tid * 5 + 0], cy = gtb[tid * 5 + 1];
        float w = gtb[tid * 5 + 2], h = gtb[tid * 5 + 3], a = gtb[tid * 5 + 4];
        sg[tid * 8 + 0] = cx; sg[tid * 8 + 1] = cy;
        sg[tid * 8 + 2] = w;  sg[tid * 8 + 3] = h;
        sg[tid * 8 + 4] = cosf(a); sg[tid * 8 + 5] = sinf(a);
        sg[tid * 8 + 7] = w * h;
        sl[tid] = glab[tid];
    }
    __syncthreads();

    int P = *((volatile int*)&g_pairCnt);
    if (P > GMX * LCAP) P = GMX * LCAP;
    int warpsTotal = (int)gridDim.x * 8;
    for (int t = blockIdx.x * 8 + wid; t < P; t += warpsTotal) {
        unsigned rec = g_pairs[t];
        int pi = (int)(rec >> 16);
        int g = (int)((rec >> 11) & 31u);
        int pos = (int)(rec & 0x7FFu);

        float2 p2 = ((const float2*)pts)[pi];
        float ppx = p2.x, ppy = p2.y;
        float pst = stride[pi];

        float bcx = sg[g * 8 + 0], bcy = sg[g * 8 + 1];
        float w = sg[g * 8 + 2], h = sg[g * 8 + 3];
        float c = sg[g * 8 + 4], s = sg[g * 8 + 5];
        float a2 = sg[g * 8 + 7];

        float offx = ppx - bcx, offy = ppy - bcy;
        float ox = offx * c + offy * s;
        float oy = -offx * s + offy * c;
        float u = 2.0f * ox / w, vv = 2.0f * oy / h;
        float cent = fmaxf(1.0f - sqrtf((u * u + vv * vv + 1e-8f) * 0.5f), 0.0f);

        float d0 = preds[pi * 5 + 0] * pst, d1 = preds[pi * 5 + 1] * pst;
        float d2 = preds[pi * 5 + 2] * pst, d3 = preds[pi * 5 + 3] * pst;
        float ang = preds[pi * 5 + 4];
        float dc = cosf(ang), ds = sinf(ang);
        float bw1 = d0 + d2, bh1 = d1 + d3;
        float otx = (d2 - d0) * 0.5f, oty = (d3 - d1) * 0.5f;
        float bcx1 = ppx + (dc * otx - ds * oty);
        float bcy1 = ppy + (ds * otx + dc * oty);
        float xm = ang + HPI_F;
        float rm = fmodf(xm, PI_F);
        if (rm < 0.0f) rm += PI_F;
        float na = rm - HPI_F;
        float bc1 = cosf(na), bs1 = sinf(na);
        float ar1 = bw1 * bh1;

        float pk = (lane < 15) ? probs[pi * 15 + lane] : -3.0e38f;
        float pm = wmaxf(pk);
        float ek = (lane < 15) ? expf(pk - pm) : 0.0f;
        float psum = wadd(ek);
        float elab = __shfl_sync(0xFFFFFFFFu, ek, sl[g]);
        float prob = elab / psum;

        float iou = riou_warp(lane, bcx1, bcy1, bw1, bh1, bc1, bs1, ar1,
                              bcx, bcy, w, h, c, s, a2);

        if (lane == 0)
            g_lv[g * LCAP + pos] = 0.2f * cent + 0.2f * iou + 0.6f * prob;
    }
}

// ---------------------------------------------------------------------------
// kOutSel (86 x 256): block 0 runs selection (validated R10 body) + resets,
// then flags g_selDone; other blocks spin (co-resident: 86 <= 148 SMs).
// All blocks then run the validated kOut body. Last block resets flags.
// ---------------------------------------------------------------------------
__global__ void __launch_bounds__(256)
kOutSel(const float* __restrict__ pts, const float* __restrict__ stride,
        const float* __restrict__ gtb, const int* __restrict__ glab,
        float* __restrict__ out, int N, int G)
{
    __shared__ float sg[GMX * 8];
    __shared__ int sl[GMX];
    __shared__ int sOvrPt[GMX];
    __shared__ int sOvrG[GMX];
    __shared__ int sOvrCnt;

    int tid = threadIdx.x;
    int lane = tid & 31;
    int wid = tid >> 5;

    if (tid < GMX) {
        if (tid < G) {
            float cx = gtb[tid * 5 + 0], cy = gtb[tid * 5 + 1];
            float w = gtb[tid * 5 + 2], h = gtb[tid * 5 + 3], a = gtb[tid * 5 + 4];
            sg[tid * 8 + 0] = cx; sg[tid * 8 + 1] = cy;
            sg[tid * 8 + 2] = w;  sg[tid * 8 + 3] = h;
            sg[tid * 8 + 4] = cosf(a); sg[tid * 8 + 5] = sinf(a);
            sg[tid * 8 + 6] = a; sg[tid * 8 + 7] = w * h;
            sl[tid] = glab[tid];
        }
        sOvrPt[tid] = -1;
    }
    __syncthreads();

    if (blockIdx.x == 0) {
        // ===== selection prologue (validated R10 kSel body) =====
        __shared__ int scnt[GMX];
        __shared__ int soff[GMX + 1];
        __shared__ unsigned long long sAK[GMX];
        __shared__ float slv[FCAP];
        __shared__ int   sli[FCAP];
        __shared__ int2 ssel[512];
        __shared__ int sSelCnt;
        __shared__ int sCounts[GMX];

        if (tid < GMX) {
            if (tid < G) {
                int n = g_cnt[tid];
                scnt[tid] = (n > LCAP) ? LCAP : n;
                sAK[tid] = g_anchorKey[tid];
            } else { scnt[tid] = 0; sAK[tid] = 0ULL; }
            sCounts[tid] = 0;
        }
        if (tid == 0) sSelCnt = 0;
        __syncthreads();

        if (tid == 0) {
            int acc = 0;
            for (int q = 0; q < GMX; ++q) { soff[q] = acc; acc += scnt[q]; }
            soff[GMX] = acc;
        }
        __syncthreads();
        int total = soff[GMX];
        bool stg = (total <= FCAP);

        if (stg) {
            for (int t = tid; t < total; t += 256) {
                int g = 0;
                while (soff[g + 1] <= t) ++g;
                int e = t - soff[g];
                slv[t] = g_lv[g * LCAP + e];
                sli[t] = g_li[g * LCAP + e];
            }
        }
        __syncthreads();

        for (int g = wid; g < G; g += 8) {
            int n = scnt[g];
            int base = soff[g];
            for (int e = lane; e < n; e += 32) {
                float v = stg ? slv[base + e] : g_lv[g * LCAP + e];
                int id  = stg ? sli[base + e] : g_li[g * LCAP + e];
                int rank = 0;
                for (int e2 = 0; e2 < n; ++e2) {
                    float v2 = stg ? slv[base + e2] : g_lv[g * LCAP + e2];
                    int id2  = stg ? sli[base + e2] : g_li[g * LCAP + e2];
                    rank += (v2 > v) || (v2 == v && id2 < id);
                }
                if (rank < TOPK_K) {
                    int pos = atomicAdd(&sSelCnt, 1);
                    ssel[pos] = make_int2(id, g);
                    atomicOr(&g_bits[id], 1u << g);
                }
            }
        }
        __threadfence();
        __syncthreads();

        int sc = sSelCnt;

        for (int t = tid; t < sc; t += 256) {
            int pi = ssel[t].x, og = ssel[t].y;
            unsigned bits = g_bits[pi];
            if ((bits & (0u - bits)) == (1u << og)) {
                float best = 0.0f; int gi = 0;
                for (int q = 0; q < G; ++q) {
                    if ((bits >> q) & 1u) {
                        float area = sg[q * 8 + 7];
                        if (area > best) { best = area; gi = q; }
                    }
                }
                atomicAdd(&sCounts[gi], 1);
            }
        }
        __syncthreads();

        if (tid == 0) {
            int oc = 0;
            for (int q = 0; q < G; ++q) {
                if (sCounts[q] == 0) {
                    unsigned long long k = sAK[q];
                    int ai = (int)(~(unsigned)(k & 0xFFFFFFFFULL));
                    if (ai >= 0 && ai < N) { g_ovrPt[oc] = ai; g_ovrG[oc] = q; ++oc; }
                }
            }
            g_ovrCnt = oc;
            g_pairCnt = 0;
        }
        __syncthreads();
        if (tid < GMX) { g_cnt[tid] = 0; g_anchorKey[tid] = 0ULL; }
        __threadfence();
        __syncthreads();
        if (tid == 0) g_selDone = 1;     // release
    } else {
        // spin until selection done (co-resident; bounded wait)
        if (tid == 0) {
            while (g_selDone == 0) __nanosleep(64);
        }
        __syncthreads();
        __threadfence();                  // acquire
    }

    // ===== output body (validated R10/R12) =====
    if (tid == 0) sOvrCnt = g_ovrCnt;
    __syncthreads();
    int oc = sOvrCnt;
    if (tid < oc) { sOvrPt[tid] = g_ovrPt[tid]; sOvrG[tid] = g_ovrG[tid]; }
    __syncthreads();

    int i = blockIdx.x * 256 + tid;
    if (i < N) {
        unsigned bits = g_bits[i];
        if (bits) g_bits[i] = 0u;    // leave clean for next replay

        float best = 0.0f; int gi = 0;
        while (bits) {
            int q = __ffs(bits) - 1;
            bits &= bits - 1u;
            float area = sg[q * 8 + 7];
            if (area > best) { best = area; gi = q; }
        }
        int label = (best == 0.0f) ? BG_LAB : sl[gi];

        for (int t = 0; t < oc; ++t) {
            if (sOvrPt[t] == i) { gi = sOvrG[t]; label = sl[gi]; }
        }

        float cx = sg[gi * 8 + 0], cy = sg[gi * 8 + 1];
        float w = sg[gi * 8 + 2], h = sg[gi * 8 + 3];
        float c = sg[gi * 8 + 4], s = sg[gi * 8 + 5];
        float ang = sg[gi * 8 + 6];
        float2 p2 = ((const float2*)pts)[i];
        float offx = p2.x - cx, offy = p2.y - cy;
        float ox = offx * c + offy * s;
        float oy = -offx * s + offy * c;
        float st = stride[i];

        out[i] = (float)label;
        out[N + i * 4 + 0] = (w * 0.5f + ox) / st;
        out[N + i * 4 + 1] = (h * 0.5f + oy) / st;
        out[N + i * 4 + 2] = (w * 0.5f - ox) / st;
        out[N + i * 4 + 3] = (h * 0.5f - oy) / st;
        out[N * 5 + i] = ang;
    }

    // flag reset by last-finishing block (all blocks have passed the spin)
    __syncthreads();
    if (tid == 0) {
        int a = atomicAdd(&g_done, 1);
        if (a == (int)gridDim.x - 1) {
            g_selDone = 0;
            g_done = 0;
            __threadfence();
        }
    }
}

// ---------------------------------------------------------------------------
extern "C" void kernel_launch(void* const* d_in, const int* in_sizes, int n_in,
                              void* d_out, int out_size)
{
    const float* points = (const float*)d_in[0];
    const float* rr     = (const float*)d_in[1];
    const float* stride = (const float*)d_in[2];
    const float* gtb    = (const float*)d_in[3];
    const int*   glab   = (const int*)d_in[4];
    const float* preds  = (const float*)d_in[5];
    const float* probs  = (const float*)d_in[6];
    float* out = (float*)d_out;

    int N = in_sizes[0] / 2;
    int G = in_sizes[3] / 5;
    if (G > GMX) G = GMX;
    if (N > NMAX) N = NMAX;

    int nb = (N + 255) / 256;
    kGate<<<nb * 2, 256>>>(points, rr, stride, gtb, N, G);
    kCost<<<128, 256>>>(points, stride, gtb, glab, preds, probs, G);
    kOutSel<<<nb, 256>>>(points, stride, gtb, glab, out, N, G);
}

// round 16
// speedup vs baseline: 1.1648x; 1.1648x over previous
#include <cuda_runtime.h>
#include <math.h>

#define GMX 32
#define GSUB 8
#define NMAX 22528
#define LCAP 2048
#define FCAP 1024
#define TOPK_K 15
#define BG_LAB 15
#define PI_F   3.14159265358979323846f
#define HPI_F  1.57079632679489661923f

// -------- persistent device scratch (zero-init; left clean each run) --------
__device__ int g_cnt[GMX];
__device__ unsigned long long g_anchorKey[GMX];
__device__ int g_pairCnt;
__device__ float g_lv[GMX * LCAP];
__device__ int   g_li[GMX * LCAP];
__device__ unsigned g_pairs[GMX * LCAP];   // packed: i<<16 | g<<11 | pos
__device__ unsigned g_bits[NMAX];
__device__ int g_ovrPt[GMX];
__device__ int g_ovrG[GMX];
__device__ int g_ovrCnt;

// ---------------------------------------------------------------------------
__device__ __forceinline__ float wadd(float v) {
#pragma unroll
    for (int off = 16; off > 0; off >>= 1) v += __shfl_xor_sync(0xFFFFFFFFu, v, off);
    return v;
}
__device__ __forceinline__ float wmaxf(float v) {
#pragma unroll
    for (int off = 16; off > 0; off >>= 1) v = fmaxf(v, __shfl_xor_sync(0xFFFFFFFFu, v, off));
    return v;
}

__device__ __forceinline__ void box_corner(int a, float cx, float cy, float w2, float h2,
                                           float c, float s, float& x, float& y) {
    float dxs = (a < 2) ? w2 : -w2;
    float dys = (a == 1 || a == 2) ? h2 : -h2;
    x = cx + dxs * c - dys * s;
    y = cy + dxs * s + dys * c;
}

// ---------------------------------------------------------------------------
// Warp-cooperative rotated IoU (validated R12). Lane k owns candidate slot k.
// ---------------------------------------------------------------------------
__device__ float riou_warp(int lane,
                           float b1cx, float b1cy, float b1w, float b1h,
                           float b1c, float b1s, float a1,
                           float b2cx, float b2cy, float b2w, float b2h,
                           float b2c, float b2s, float a2)
{
    {
        float ddx = b1cx - b2cx, ddy = b1cy - b2cy;
        float r1 = 0.5f * sqrtf(b1w * b1w + b1h * b1h);
        float r2 = 0.5f * sqrtf(b2w * b2w + b2h * b2h);
        float rrs = r1 + r2 + 0.5f;
        if (ddx * ddx + ddy * ddy > rrs * rrs) return 0.0f;
    }
    float w12 = b1w * 0.5f, h12 = b1h * 0.5f;
    float w22 = b2w * 0.5f, h22 = b2h * 0.5f;

    float ptx = 0.0f, pty = 0.0f;
    bool ok = false;

    if (lane < 16) {
        int a = lane >> 2, b = lane & 3;
        float px, py, pnx, pny, qx, qy, qnx, qny;
        box_corner(a, b1cx, b1cy, w12, h12, b1c, b1s, px, py);
        box_corner((a + 1) & 3, b1cx, b1cy, w12, h12, b1c, b1s, pnx, pny);
        box_corner(b, b2cx, b2cy, w22, h22, b2c, b2s, qx, qy);
        box_corner((b + 1) & 3, b2cx, b2cy, w22, h22, b2c, b2s, qnx, qny);
        float d1x = pnx - px, d1y = pny - py;
        float d2x = qnx - qx, d2y = qny - qy;
        float den = d1x * d2y - d1y * d2x;
        bool dok = fabsf(den) > 1e-10f;
        float safe = dok ? den : 1.0f;
        float qpx = qx - px, qpy = qy - py;
        float t = (qpx * d2y - qpy * d2x) / safe;
        float u = (qpx * d1y - qpy * d1x) / safe;
        ok = dok && t >= 0.0f && t <= 1.0f && u >= 0.0f && u <= 1.0f;
        ptx = px + t * d1x; pty = py + t * d1y;
    } else if (lane < 20) {
        int a = lane - 16;
        box_corner(a, b1cx, b1cy, w12, h12, b1c, b1s, ptx, pty);
        float rx = ptx - b2cx, ry = pty - b2cy;
        float xx = rx * b2c + ry * b2s;
        float yy = -rx * b2s + ry * b2c;
        ok = (fabsf(xx) <= w22 + 1e-6f) && (fabsf(yy) <= h22 + 1e-6f);
    } else if (lane < 24) {
        int b = lane - 20;
        box_corner(b, b2cx, b2cy, w22, h22, b2c, b2s, ptx, pty);
        float rx = ptx - b1cx, ry = pty - b1cy;
        float xx = rx * b1c + ry * b1s;
        float yy = -rx * b1s + ry * b1c;
        ok = (fabsf(xx) <= w12 + 1e-6f) && (fabsf(yy) <= h12 + 1e-6f);
    }

    unsigned okm = __ballot_sync(0xFFFFFFFFu, ok) & 0xFFFFFFu;
    if (okm == 0u) return 0.0f;
    int cnt = __popc(okm);

    float ctrx = wadd(ok ? ptx : 0.0f) / (float)cnt;
    float ctry = wadd(ok ? pty : 0.0f) / (float)cnt;

    float vx = ptx - ctrx, vy = pty - ctry;
    float dnm = fabsf(vx) + fabsf(vy);
    float pa = ok ? ((dnm == 0.0f) ? 0.0f : copysignf(1.0f - vx / dnm, vy)) : 3.0e38f;

    float mA = 3.0e38f, mX = 0.0f, mY = 0.0f;
    float bA = 3.0e38f, bX = 0.0f, bY = 0.0f;
    bool bFound = false;
#pragma unroll
    for (int j = 0; j < 24; ++j) {
        float paj = __shfl_sync(0xFFFFFFFFu, pa, j);
        float pxj = __shfl_sync(0xFFFFFFFFu, ptx, j);
        float pyj = __shfl_sync(0xFFFFFFFFu, pty, j);
        bool okj = (okm >> j) & 1u;
        if (okj && paj < mA) { mA = paj; mX = pxj; mY = pyj; }
        bool gtk = (paj > pa) || (paj == pa && j > lane);
        if (okj && gtk && paj < bA) { bA = paj; bX = pxj; bY = pyj; bFound = true; }
    }
    if (!bFound) { bX = mX; bY = mY; }

    float cross = 0.0f;
    if (ok) {
        float vbx = bX - ctrx, vby = bY - ctry;
        cross = vx * vby - vy * vbx;
    }
    float acc = wadd(cross);
    float inter = 0.5f * fabsf(acc);
    return inter / fmaxf(a1 + a2 - inter, 1e-8f);
}

// ---------------------------------------------------------------------------
// kGate: 4 blocks per 256-point chunk (8 gts each) -> grid 4*nb for higher
// warps/SM. Prune-gated gating + anchor + pair emission.
// ---------------------------------------------------------------------------
__global__ void __launch_bounds__(256)
kGate(const float* __restrict__ pts, const float* __restrict__ rr,
      const float* __restrict__ stride, const float* __restrict__ gtb,
      int N, int G)
{
    __shared__ float sg[GSUB * 8];
    __shared__ unsigned long long sA[GSUB];

    int tid = threadIdx.x;
    int sub = blockIdx.x & 3;
    int pb = blockIdx.x >> 2;
    int g0 = sub * GSUB;
    int gn = G - g0; if (gn > GSUB) gn = GSUB; if (gn < 0) gn = 0;

    if (tid < GSUB) {
        sA[tid] = 0ULL;
        if (tid < gn) {
            int gg = g0 + tid;
            float cx = gtb[gg * 5 + 0], cy = gtb[gg * 5 + 1];
            float w = gtb[gg * 5 + 2], h = gtb[gg * 5 + 3], a = gtb[gg * 5 + 4];
            sg[tid * 8 + 0] = cx; sg[tid * 8 + 1] = cy;
            sg[tid * 8 + 2] = w;  sg[tid * 8 + 3] = h;
            sg[tid * 8 + 4] = cosf(a); sg[tid * 8 + 5] = sinf(a);
            float mwh = fmaxf(w, h);
            sg[tid * 8 + 6] = 0.5f * mwh * mwh;
        } else {
            sg[tid * 8 + 0] = -1e30f; sg[tid * 8 + 1] = -1e30f;
            sg[tid * 8 + 6] = 0.0f;
        }
    }
    __syncthreads();

    int i = pb * 256 + tid;
    bool inb = (i < N);

    float px = 0.f, py = 0.f, st = 1.f, r0 = 0.f, r1 = 0.f;
    if (inb) {
        float2 p2 = ((const float2*)pts)[i];
        float2 rr2 = ((const float2*)rr)[i];
        px = p2.x; py = p2.y;
        st = stride[i];
        r0 = rr2.x; r1 = rr2.y;
    }
    float crad = 1.5f * st;

    unsigned mask = 0u;
    if (inb) {
        for (int g = 0; g < gn; ++g) {
            float dx = px - sg[g * 8 + 0], dy = py - sg[g * 8 + 1];
            if (dx * dx + dy * dy >= sg[g * 8 + 6]) continue;   // exact skip (validated)

            float w = sg[g * 8 + 2], h = sg[g * 8 + 3];
            float c = sg[g * 8 + 4], s = sg[g * 8 + 5];
            float ox = dx * c + dy * s;
            float oy = -dx * s + dy * c;
            float t0 = w * 0.5f + ox, t1 = h * 0.5f + oy;
            float t2 = w * 0.5f - ox, t3 = h * 0.5f - oy;
            float mn = fminf(fminf(t0, t1), fminf(t2, t3));
            float mx = fmaxf(fmaxf(t0, t1), fmaxf(t2, t3));
            float u = 2.0f * ox / w, v = 2.0f * oy / h;
            float cent = fmaxf(1.0f - sqrtf((u * u + v * v + 1e-8f) * 0.5f), 0.0f);
            bool valid = (mn > 0.0f) && (fabsf(ox) < crad) && (fabsf(oy) < crad)
                         && (mx >= r0) && (mx <= r1);
            if (valid) mask |= 1u << g;

            if (cent > 0.0f) {
                unsigned long long key =
                    ((unsigned long long)__float_as_uint(cent) << 32) | (unsigned)(~(unsigned)i);
                if (key > *((volatile unsigned long long*)&sA[g]))
                    atomicMax(&sA[g], key);
            }
        }
    }
    __syncthreads();
    if (tid < gn) {
        unsigned long long v = sA[tid];
        if (v != 0ULL) atomicMax(&g_anchorKey[g0 + tid], v);
    }

    while (mask) {
        int g = __ffs(mask) - 1;
        mask &= mask - 1u;
        int gg = g0 + g;
        int pos = atomicAdd(&g_cnt[gg], 1);
        int ppos = atomicAdd(&g_pairCnt, 1);
        if (pos < LCAP && ppos < GMX * LCAP) {
            g_li[gg * LCAP + pos] = i;
            g_pairs[ppos] = ((unsigned)i << 16) | ((unsigned)gg << 11) | (unsigned)pos;
        }
    }
}

// ---------------------------------------------------------------------------
// kCost: warp per pair (validated R12) + early block exit when no work.
// ---------------------------------------------------------------------------
__global__ void __launch_bounds__(256)
kCost(const float* __restrict__ pts, const float* __restrict__ stride,
      const float* __restrict__ gtb, const int* __restrict__ glab,
      const float* __restrict__ preds, const float* __restrict__ probs, int G)
{
    __shared__ float sg[GMX * 8];
    __shared__ int sl[GMX];
    int tid = threadIdx.x;
    int lane = tid & 31;
    int wid = tid >> 5;

    int P = *((volatile int*)&g_pairCnt);
    if (P > GMX * LCAP) P = GMX * LCAP;
    if (blockIdx.x * 8 >= P) return;     // no pairs for this block

    if (tid < G) {
        float cx = gtb[tid * 5 + 0], cy = gtb[tid * 5 + 1];
        float w = gtb[tid * 5 + 2], h = gtb[tid * 5 + 3], a = gtb[tid * 5 + 4];
        sg[tid * 8 + 0] = cx; sg[tid * 8 + 1] = cy;
        sg[tid * 8 + 2] = w;  sg[tid * 8 + 3] = h;
        sg[tid * 8 + 4] = cosf(a); sg[tid * 8 + 5] = sinf(a);
        sg[tid * 8 + 7] = w * h;
        sl[tid] = glab[tid];
    }
    __syncthreads();

    int warpsTotal = (int)gridDim.x * 8;
    for (int t = blockIdx.x * 8 + wid; t < P; t += warpsTotal) {
        unsigned rec = g_pairs[t];
        int pi = (int)(rec >> 16);
        int g = (int)((rec >> 11) & 31u);
        int pos = (int)(rec & 0x7FFu);

        float2 p2 = ((const float2*)pts)[pi];
        float ppx = p2.x, ppy = p2.y;
        float pst = stride[pi];

        float bcx = sg[g * 8 + 0], bcy = sg[g * 8 + 1];
        float w = sg[g * 8 + 2], h = sg[g * 8 + 3];
        float c = sg[g * 8 + 4], s = sg[g * 8 + 5];
        float a2 = sg[g * 8 + 7];

        float offx = ppx - bcx, offy = ppy - bcy;
        float ox = offx * c + offy * s;
        float oy = -offx * s + offy * c;
        float u = 2.0f * ox / w, vv = 2.0f * oy / h;
        float cent = fmaxf(1.0f - sqrtf((u * u + vv * vv + 1e-8f) * 0.5f), 0.0f);

        float d0 = preds[pi * 5 + 0] * pst, d1 = preds[pi * 5 + 1] * pst;
        float d2 = preds[pi * 5 + 2] * pst, d3 = preds[pi * 5 + 3] * pst;
        float ang = preds[pi * 5 + 4];
        float dc = cosf(ang), ds = sinf(ang);
        float bw1 = d0 + d2, bh1 = d1 + d3;
        float otx = (d2 - d0) * 0.5f, oty = (d3 - d1) * 0.5f;
        float bcx1 = ppx + (dc * otx - ds * oty);
        float bcy1 = ppy + (ds * otx + dc * oty);
        float xm = ang + HPI_F;
        float rm = fmodf(xm, PI_F);
        if (rm < 0.0f) rm += PI_F;
        float na = rm - HPI_F;
        float bc1 = cosf(na), bs1 = sinf(na);
        float ar1 = bw1 * bh1;

        float pk = (lane < 15) ? probs[pi * 15 + lane] : -3.0e38f;
        float pm = wmaxf(pk);
        float ek = (lane < 15) ? expf(pk - pm) : 0.0f;
        float psum = wadd(ek);
        float elab = __shfl_sync(0xFFFFFFFFu, ek, sl[g]);
        float prob = elab / psum;

        float iou = riou_warp(lane, bcx1, bcy1, bw1, bh1, bc1, bs1, ar1,
                              bcx, bcy, w, h, c, s, a2);

        if (lane == 0)
            g_lv[g * LCAP + pos] = 0.2f * cent + 0.2f * iou + 0.6f * prob;
    }
}

// ---------------------------------------------------------------------------
// kSel (1 block, 256 thr): selection once. [validated R10/R12] + resets.
// ---------------------------------------------------------------------------
__global__ void __launch_bounds__(256)
kSel(const float* __restrict__ gtb, int N, int G)
{
    __shared__ int scnt[GMX];
    __shared__ int soff[GMX + 1];
    __shared__ unsigned long long sAK[GMX];
    __shared__ float sarea[GMX];
    __shared__ float slv[FCAP];
    __shared__ int   sli[FCAP];
    __shared__ int2 ssel[512];
    __shared__ int sSelCnt;
    __shared__ int sCounts[GMX];

    int tid = threadIdx.x;
    int lane = tid & 31;
    int wid = tid >> 5;

    if (tid < GMX) {
        if (tid < G) {
            int n = g_cnt[tid];
            scnt[tid] = (n > LCAP) ? LCAP : n;
            sAK[tid] = g_anchorKey[tid];
            sarea[tid] = gtb[tid * 5 + 2] * gtb[tid * 5 + 3];
        } else { scnt[tid] = 0; sAK[tid] = 0ULL; sarea[tid] = 0.0f; }
        sCounts[tid] = 0;
    }
    if (tid == 0) sSelCnt = 0;
    __syncthreads();

    if (tid == 0) {
        int acc = 0;
        for (int q = 0; q < GMX; ++q) { soff[q] = acc; acc += scnt[q]; }
        soff[GMX] = acc;
    }
    __syncthreads();
    int total = soff[GMX];
    bool stg = (total <= FCAP);

    if (stg) {
        for (int t = tid; t < total; t += 256) {
            int g = 0;
            while (soff[g + 1] <= t) ++g;
            int e = t - soff[g];
            slv[t] = g_lv[g * LCAP + e];
            sli[t] = g_li[g * LCAP + e];
        }
    }
    __syncthreads();

    for (int g = wid; g < G; g += 8) {
        int n = scnt[g];
        int base = soff[g];
        for (int e = lane; e < n; e += 32) {
            float v = stg ? slv[base + e] : g_lv[g * LCAP + e];
            int id  = stg ? sli[base + e] : g_li[g * LCAP + e];
            int rank = 0;
            for (int e2 = 0; e2 < n; ++e2) {
                float v2 = stg ? slv[base + e2] : g_lv[g * LCAP + e2];
                int id2  = stg ? sli[base + e2] : g_li[g * LCAP + e2];
                rank += (v2 > v) || (v2 == v && id2 < id);
            }
            if (rank < TOPK_K) {
                int pos = atomicAdd(&sSelCnt, 1);
                ssel[pos] = make_int2(id, g);
                atomicOr(&g_bits[id], 1u << g);
            }
        }
    }
    __threadfence_block();
    __syncthreads();

    int sc = sSelCnt;

    for (int t = tid; t < sc; t += 256) {
        int pi = ssel[t].x, og = ssel[t].y;
        unsigned bits = g_bits[pi];
        if ((bits & (0u - bits)) == (1u << og)) {
            float best = 0.0f; int gi = 0;
            for (int q = 0; q < G; ++q) {
                if ((bits >> q) & 1u) {
                    float area = sarea[q];
                    if (area > best) { best = area; gi = q; }
                }
            }
            atomicAdd(&sCounts[gi], 1);
        }
    }
    __syncthreads();

    if (tid == 0) {
        int oc = 0;
        for (int q = 0; q < G; ++q) {
            if (sCounts[q] == 0) {
                unsigned long long k = sAK[q];
                int ai = (int)(~(unsigned)(k & 0xFFFFFFFFULL));
                if (ai >= 0 && ai < N) { g_ovrPt[oc] = ai; g_ovrG[oc] = q; ++oc; }
            }
        }
        g_ovrCnt = oc;
        g_pairCnt = 0;
    }

    __syncthreads();
    if (tid < GMX) { g_cnt[tid] = 0; g_anchorKey[tid] = 0ULL; }
}

// ---------------------------------------------------------------------------
// kOut (2*nb x 128): per-point finalization, smaller blocks for more
// blocks/SM.  [validated body R10/R12]
// ---------------------------------------------------------------------------
__global__ void __launch_bounds__(128)
kOut(const float* __restrict__ pts, const float* __restrict__ stride,
     const float* __restrict__ gtb, const int* __restrict__ glab,
     float* __restrict__ out, int N, int G)
{
    __shared__ float sg[GMX * 8];
    __shared__ int sl[GMX];
    __shared__ int sOvrPt[GMX];
    __shared__ int sOvrG[GMX];
    __shared__ int sOvrCnt;

    int tid = threadIdx.x;
    if (tid < GMX) {
        if (tid < G) {
            float cx = gtb[tid * 5 + 0], cy = gtb[tid * 5 + 1];
            float w = gtb[tid * 5 + 2], h = gtb[tid * 5 + 3], a = gtb[tid * 5 + 4];
            sg[tid * 8 + 0] = cx; sg[tid * 8 + 1] = cy;
            sg[tid * 8 + 2] = w;  sg[tid * 8 + 3] = h;
            sg[tid * 8 + 4] = cosf(a); sg[tid * 8 + 5] = sinf(a);
            sg[tid * 8 + 6] = a; sg[tid * 8 + 7] = w * h;
            sl[tid] = glab[tid];
        }
        sOvrPt[tid] = -1;
    }
    if (tid == 0) sOvrCnt = g_ovrCnt;
    __syncthreads();
    int oc = sOvrCnt;
    if (tid < oc) { sOvrPt[tid] = g_ovrPt[tid]; sOvrG[tid] = g_ovrG[tid]; }
    __syncthreads();

    int i = blockIdx.x * 128 + tid;
    if (i >= N) return;

    unsigned bits = g_bits[i];
    if (bits) g_bits[i] = 0u;    // leave clean for next replay

    float best = 0.0f; int gi = 0;
    while (bits) {
        int q = __ffs(bits) - 1;
        bits &= bits - 1u;
        float area = sg[q * 8 + 7];
        if (area > best) { best = area; gi = q; }
    }
    int label = (best == 0.0f) ? BG_LAB : sl[gi];

    for (int t = 0; t < oc; ++t) {
        if (sOvrPt[t] == i) { gi = sOvrG[t]; label = sl[gi]; }
    }

    float cx = sg[gi * 8 + 0], cy = sg[gi * 8 + 1];
    float w = sg[gi * 8 + 2], h = sg[gi * 8 + 3];
    float c = sg[gi * 8 + 4], s = sg[gi * 8 + 5];
    float ang = sg[gi * 8 + 6];
    float2 p2 = ((const float2*)pts)[i];
    float offx = p2.x - cx, offy = p2.y - cy;
    float ox = offx * c + offy * s;
    float oy = -offx * s + offy * c;
    float st = stride[i];

    out[i] = (float)label;
    out[N + i * 4 + 0] = (w * 0.5f + ox) / st;
    out[N + i * 4 + 1] = (h * 0.5f + oy) / st;
    out[N + i * 4 + 2] = (w * 0.5f - ox) / st;
    out[N + i * 4 + 3] = (h * 0.5f - oy) / st;
    out[N * 5 + i] = ang;
}

// ---------------------------------------------------------------------------
extern "C" void kernel_launch(void* const* d_in, const int* in_sizes, int n_in,
                              void* d_out, int out_size)
{
    const float* points = (const float*)d_in[0];
    const float* rr     = (const float*)d_in[1];
    const float* stride = (const float*)d_in[2];
    const float* gtb    = (const float*)d_in[3];
    const int*   glab   = (const int*)d_in[4];
    const float* preds  = (const float*)d_in[5];
    const float* probs  = (const float*)d_in[6];
    float* out = (float*)d_out;

    int N = in_sizes[0] / 2;
    int G = in_sizes[3] / 5;
    if (G > GMX) G = GMX;
    if (N > NMAX) N = NMAX;

    int nb = (N + 255) / 256;
    kGate<<<nb * 4, 256>>>(points, rr, stride, gtb, N, G);
    kCost<<<128, 256>>>(points, stride, gtb, glab, preds, probs, G);
    kSel<<<1, 256>>>(gtb, N, G);
    kOut<<<(N + 127) / 128, 128>>>(points, stride, gtb, glab, out, N, G);
}